// round 16
// baseline (speedup 1.0000x reference)
#include <cuda_runtime.h>
#include <cuda_fp16.h>
#include <cstdint>

// Problem constants
#define BB 256
#define DD 10
#define PP 1152
#define OO 16
#define DOX 160            // D*O
#define II 8
#define PCH 8              // p per chunk in k_uhat
#define NCH (PP / PCH)     // 144
#define BGRP 64            // b per CTA in k_uhat
#define NBG (BB / BGRP)    // 4
#define HP (PP / 2)        // 576 p per cluster half
#define HCH (NCH / 2)      // 72 s1p chunks per half
#define WROWS (HP / 8)     // 72 rows per warp per pass
#define NT (WROWS / 4)     // 18 four-row tiles per warp per pass
#define ROWPAD 352         // padded smem row stride (bytes)

// Scratch
__device__ __half g_uhat_h[(size_t)BB * PP * DOX + 64 * DOX];  // 94.4 MB
__device__ float g_s1p[(size_t)BB * NCH * DOX];                // 23.6 MB

// ---------------------------------------------------------------------------
// Kernel 1: u_hat = W.x (fp16 math + store) + per-chunk fp32 s1 partials.
// Grid (NCH, NBG) x 160 threads.  (~23 us, validated)
// ---------------------------------------------------------------------------
__global__ void __launch_bounds__(DOX) k_uhat(const float* __restrict__ x,
                                              const float* __restrict__ W) {
    const int c = blockIdx.x;
    const int t = threadIdx.x;
    const int d = t >> 4;
    const int o = t & 15;
    const int p0 = c * PCH;
    const int b0 = blockIdx.y * BGRP;

    __half2 w2[PCH][4];
#pragma unroll
    for (int ps = 0; ps < PCH; ps++) {
        const float4* wp = reinterpret_cast<const float4*>(
            W + (((size_t)d * PP + (size_t)(p0 + ps)) * OO + o) * II);
        float4 wa = wp[0], wb = wp[1];
        w2[ps][0] = __floats2half2_rn(wa.x, wa.y);
        w2[ps][1] = __floats2half2_rn(wa.z, wa.w);
        w2[ps][2] = __floats2half2_rn(wb.x, wb.y);
        w2[ps][3] = __floats2half2_rn(wb.z, wb.w);
    }

    __shared__ uint4 xs4[BGRP * PCH];   // 8 KB
    for (int idx = t; idx < BGRP * PCH; idx += DOX) {
        int bb = idx >> 3;
        int ps = idx & 7;
        const float4* xp = reinterpret_cast<const float4*>(
            x + ((size_t)(b0 + bb) * PP + (size_t)(p0 + ps)) * II);
        float4 xa = xp[0], xb = xp[1];
        uint4 h;
        reinterpret_cast<__half2*>(&h)[0] = __floats2half2_rn(xa.x, xa.y);
        reinterpret_cast<__half2*>(&h)[1] = __floats2half2_rn(xa.z, xa.w);
        reinterpret_cast<__half2*>(&h)[2] = __floats2half2_rn(xb.x, xb.y);
        reinterpret_cast<__half2*>(&h)[3] = __floats2half2_rn(xb.z, xb.w);
        xs4[idx] = h;
    }
    __syncthreads();

    for (int bb = 0; bb < BGRP; bb++) {
        float acc = 0.f;
        __half* ud = g_uhat_h + ((size_t)(b0 + bb) * PP + p0) * DOX + t;
#pragma unroll
        for (int ps = 0; ps < PCH; ps++) {
            uint4 xr = xs4[bb * PCH + ps];
            __half2 a = __hmul2(w2[ps][0], *reinterpret_cast<__half2*>(&xr.x));
            a = __hfma2(w2[ps][1], *reinterpret_cast<__half2*>(&xr.y), a);
            a = __hfma2(w2[ps][2], *reinterpret_cast<__half2*>(&xr.z), a);
            a = __hfma2(w2[ps][3], *reinterpret_cast<__half2*>(&xr.w), a);
            __half u = __hadd(__low2half(a), __high2half(a));
            ud[(size_t)ps * DOX] = u;
            acc += __half2float(u);
        }
        g_s1p[((size_t)(b0 + bb) * NCH + c) * DOX + t] = acc;
    }
}

// ---------------------------------------------------------------------------
// Helpers
// ---------------------------------------------------------------------------
__device__ __forceinline__ unsigned smem_u32(const void* p) {
    unsigned a;
    asm("{ .reg .u64 tmp; cvta.to.shared.u64 tmp, %1; cvt.u32.u64 %0, tmp; }"
        : "=r"(a) : "l"(p));
    return a;
}
__device__ __forceinline__ float ld_peer_f32(unsigned local_addr, unsigned rank) {
    unsigned ra;
    asm("mapa.shared::cluster.u32 %0, %1, %2;" : "=r"(ra) : "r"(local_addr), "r"(rank));
    float v;
    asm volatile("ld.shared::cluster.f32 %0, [%1];" : "=f"(v) : "r"(ra));
    return v;
}
__device__ __forceinline__ void cluster_sync() {
    asm volatile("barrier.cluster.arrive.aligned;" ::: "memory");
    asm volatile("barrier.cluster.wait.aligned;" ::: "memory");
}
__device__ __forceinline__ float squash_scale16(float s) {
    float sq = s * s;
    sq += __shfl_xor_sync(0xffffffffu, sq, 1);
    sq += __shfl_xor_sync(0xffffffffu, sq, 2);
    sq += __shfl_xor_sync(0xffffffffu, sq, 4);
    sq += __shfl_xor_sync(0xffffffffu, sq, 8);
    return sq / ((1.f + sq) * sqrtf(sq + 1e-7f));
}
__device__ __forceinline__ float expp(float xv) {
    float r = fmaf(xv, 1.f / 24.f, 1.f / 6.f);
    r = fmaf(r, xv, 0.5f);
    r = fmaf(r, xv, 1.f);
    r = fmaf(r, xv, 1.f);
    return r;
}
__device__ __forceinline__ void unp8(__half2* u, uint4 ra, uint4 rb) {
    u[0] = *reinterpret_cast<const __half2*>(&ra.x);
    u[1] = *reinterpret_cast<const __half2*>(&ra.y);
    u[2] = *reinterpret_cast<const __half2*>(&ra.z);
    u[3] = *reinterpret_cast<const __half2*>(&ra.w);
    u[4] = *reinterpret_cast<const __half2*>(&rb.x);
    u[5] = *reinterpret_cast<const __half2*>(&rb.y);
    u[6] = *reinterpret_cast<const __half2*>(&rb.z);
    u[7] = *reinterpret_cast<const __half2*>(&rb.w);
}
__device__ __forceinline__ float dot16(const __half2* u, const __half2* vh) {
    __half2 h0 = __hmul2(u[0], vh[0]);
    __half2 h1 = __hmul2(u[1], vh[1]);
    h0 = __hfma2(u[2], vh[2], h0);
    h1 = __hfma2(u[3], vh[3], h1);
    h0 = __hfma2(u[4], vh[4], h0);
    h1 = __hfma2(u[5], vh[5], h1);
    h0 = __hfma2(u[6], vh[6], h0);
    h1 = __hfma2(u[7], vh[7], h1);
    float2 hf = __half22float2(__hadd2(h0, h1));
    return hf.x + hf.y;
}
__device__ __forceinline__ uint4 lds128(unsigned addr) {
    uint4 r;
    asm volatile("ld.shared.v4.u32 {%0,%1,%2,%3}, [%4];"
                 : "=r"(r.x), "=r"(r.y), "=r"(r.z), "=r"(r.w) : "r"(addr));
    return r;
}
// Copy one 4-row (1280B) tile, warp-cooperative, coalesced, into padded smem.
__device__ __forceinline__ void copy_tile(unsigned sdst, const __half* uwarp,
                                          int tile, int lane) {
    const char* g = reinterpret_cast<const char*>(uwarp) + (size_t)tile * 4 * 320;
#pragma unroll
    for (int c0 = 0; c0 < 3; c0++) {
        int c = lane + c0 * 32;
        if (c < 80) {
            int row = c / 20;
            int off = (c % 20) * 16;
            unsigned dst = sdst + row * ROWPAD + off;
            asm volatile("cp.async.ca.shared.global [%0], [%1], 16;"
                         :: "r"(dst), "l"(g + c * 16) : "memory");
        }
    }
}

// ---------------------------------------------------------------------------
// Kernel 2: fused routing, 2-CTA cluster per b. Warp owns 72 contiguous
// p-rows; double-buffered warp-private cp.async tiles (4 rows each), LDS
// reads, no CTA barriers in the mainloop. Grid 2*BB x 256 threads.
// ---------------------------------------------------------------------------
__global__ void __launch_bounds__(256, 4) __cluster_dims__(2, 1, 1)
k_route(float* __restrict__ out) {
    const int b = blockIdx.x >> 1;
    const unsigned half = blockIdx.x & 1;
    const unsigned peer = half ^ 1u;
    const int t = threadIdx.x;
    const int lane = t & 31;
    const int wid = t >> 5;              // 0..7
    const int ph = lane >> 4;            // row parity within a tile pair
    const int d = lane & 15;
    const bool valid = d < DD;
    const int dd = valid ? d : 0;

    __shared__ float vsm[DOX];
    __shared__ float v1sm[DOX];
    __shared__ float sred[8 * DOX];      // 5 KB
    __shared__ float xbuf[3][DOX];
    __shared__ __align__(16) unsigned char tbuf[8][2][4 * ROWPAD];  // 22 KB

    // ---- stage 0: v1 from s1p (my half of chunks) ----
    {
        float s = 0.f;
        if (t < DOX) {
            const float* sp = g_s1p + ((size_t)b * NCH + half * HCH) * DOX + t;
#pragma unroll 8
            for (int c = 0; c < HCH; c++) s += sp[(size_t)c * DOX];
            xbuf[0][t] = s;
        }
        cluster_sync();
        if (t < DOX) {
            float tot = s + ld_peer_f32(smem_u32(&xbuf[0][t]), peer);
            tot *= 0.1f;
            float v = tot * squash_scale16(tot);
            v1sm[t] = v;
            vsm[t] = v;
        }
        __syncthreads();
    }

    // warp's 72 contiguous rows of this half
    const __half* uwarp = g_uhat_h + ((size_t)b * PP + (size_t)half * HP
                                      + (size_t)wid * WROWS) * DOX;
    const unsigned sb0 = smem_u32(&tbuf[wid][0][0]);
    const unsigned sb1 = smem_u32(&tbuf[wid][1][0]);
    const __half2 hzero = __half2half2(__ushort_as_half((unsigned short)0));
    const unsigned ldoff = dd * 32;      // lane's byte offset within a row

    for (int pass = 0; pass < 2; pass++) {
        __half2 vh[8];
#pragma unroll
        for (int j = 0; j < 8; j++)
            vh[j] = __floats2half2_rn(vsm[dd * OO + 2 * j], vsm[dd * OO + 2 * j + 1]);

        float saf[16];
#pragma unroll
        for (int j = 0; j < 16; j++) saf[j] = 0.f;
        __half2 sa16[8];
#pragma unroll
        for (int j = 0; j < 8; j++) sa16[j] = hzero;

        // prologue: stage tile 0
        copy_tile(sb0, uwarp, 0, lane);
        asm volatile("cp.async.commit_group;" ::: "memory");

#pragma unroll 2
        for (int tk = 0; tk < NT; tk++) {
            const unsigned scur = (tk & 1) ? sb1 : sb0;
            const unsigned snxt = (tk & 1) ? sb0 : sb1;
            if (tk + 1 < NT) copy_tile(snxt, uwarp, tk + 1, lane);
            asm volatile("cp.async.commit_group;" ::: "memory");
            asm volatile("cp.async.wait_group 1;" ::: "memory");
            __syncwarp();

#pragma unroll
            for (int j = 0; j < 2; j++) {
                unsigned a = scur + (unsigned)(2 * j + ph) * ROWPAD + ldoff;
                uint4 ra = lds128(a);
                uint4 rb = lds128(a + 16);
                __half2 u2[8];
                unp8(u2, ra, rb);

                float uv = dot16(u2, vh);
                float e = valid ? expp(uv) : 0.f;
                float tot = e;
                tot += __shfl_xor_sync(0xffffffffu, tot, 1);
                tot += __shfl_xor_sync(0xffffffffu, tot, 2);
                tot += __shfl_xor_sync(0xffffffffu, tot, 4);
                tot += __shfl_xor_sync(0xffffffffu, tot, 8);
                float cc = __fdividef(e, tot);

                __half2 cch = __half2half2(__float2half_rn(cc));
#pragma unroll
                for (int jj = 0; jj < 8; jj++) sa16[jj] = __hfma2(cch, u2[jj], sa16[jj]);

                // flush fp16 segment to fp32 every 6 iterations (k = tk*2+j)
                if (((tk * 2 + j) % 6) == 5) {
#pragma unroll
                    for (int jj = 0; jj < 8; jj++) {
                        float2 f = __half22float2(sa16[jj]);
                        saf[2 * jj] += f.x;
                        saf[2 * jj + 1] += f.y;
                        sa16[jj] = hzero;
                    }
                }
            }
            __syncwarp();   // all lanes done with scur before it is overwritten
        }
        asm volatile("cp.async.wait_group 0;" ::: "memory");

        // epilogue: combine row-parity halves, publish per-warp partials
#pragma unroll
        for (int j = 0; j < 16; j++) saf[j] += __shfl_xor_sync(0xffffffffu, saf[j], 16);
        if (ph == 0 && valid) {
#pragma unroll
            for (int j = 0; j < 16; j++) sred[wid * DOX + d * OO + j] = saf[j];
        }
        __syncthreads();

        float s = 0.f;
        if (t < DOX) {
#pragma unroll
            for (int ww = 0; ww < 8; ww++) s += sred[ww * DOX + t];
            xbuf[pass + 1][t] = s;
        }
        cluster_sync();
        if (t < DOX) {
            float tot = s + ld_peer_f32(smem_u32(&xbuf[pass + 1][t]), peer);
            float v = tot * squash_scale16(tot);
            if (pass == 0) vsm[t] = v1sm[t] + v;
            else if (half == 0) out[(size_t)b * DOX + t] = v;
        }
        __syncthreads();
    }
    cluster_sync();   // keep smem alive until peer's last DSMEM read completes
}

// ---------------------------------------------------------------------------
extern "C" void kernel_launch(void* const* d_in, const int* in_sizes, int n_in,
                              void* d_out, int out_size) {
    const float* x = (const float*)d_in[0];   // [256, 1152, 8]
    const float* W = (const float*)d_in[1];   // [1, 10, 1152, 16, 8]
    float* out = (float*)d_out;               // [256, 10, 16]
    (void)in_sizes; (void)n_in; (void)out_size;

    k_uhat<<<dim3(NCH, NBG), DOX>>>(x, W);
    k_route<<<2 * BB, 256>>>(out);
}